// round 13
// baseline (speedup 1.0000x reference)
#include <cuda_runtime.h>
#include <cuda_bf16.h>
#include <math.h>

#define FULLMASK 0xffffffffu

static const int N_ROI = 116;
static const int G     = 128;
static const int DEG   = 32;
static const int NN    = G * N_ROI;        // 14848 nodes
static const int EE    = G * N_ROI * DEG;  // 475136 edges
static const int EPG   = N_ROI * DEG;      // 3712 edges per graph
static const int HID   = 64;
static const int HC    = 256;
static const int MAXDEG = 192;

// grid partition for the fused prologue
static const int PB_EMBED = NN / 16;            // 928
static const int PB_ADJ   = PB_EMBED + G;       // 1056
static const int PB_EA    = PB_ADJ + EE / 256;  // 2912
static const int PB_TOTAL = PB_EA + 1;          // 2913

// ---------------- device scratch (allocation-free) ----------------
__device__ float  g_h0[NN * HID];
__device__ float  g_h1[NN * HID];
__device__ float  g_xl[NN * HC];
__device__ float  g_xr[NN * HC];
__device__ float  g_out[NN * HC];
__device__ int    g_nodelist[NN * MAXDEG];
__device__ int    g_srclist[NN * MAXDEG];
__device__ int    g_deg[NN];
__device__ float4 g_ea4[EE];
__device__ float  g_ea1[EE];
__device__ double g_csum0[HC];
__device__ double g_csq0[HC];
__device__ double g_csum1[HC];
__device__ double g_csq1[HC];

// ---------------- f32x2 packed-FMA helpers (Blackwell) ----------------
__device__ __forceinline__ unsigned long long pk2(float lo, float hi) {
    unsigned long long r;
    asm("mov.b64 %0, {%1, %2};" : "=l"(r) : "f"(lo), "f"(hi));
    return r;
}
__device__ __forceinline__ void ffma2(unsigned long long& d, unsigned long long a,
                                      unsigned long long b) {
    asm("fma.rn.f32x2 %0, %1, %2, %0;" : "+l"(d) : "l"(a), "l"(b));
}
__device__ __forceinline__ void unpk2(float& lo, float& hi, unsigned long long v) {
    asm("mov.b64 {%0, %1}, %2;" : "=f"(lo), "=f"(hi) : "l"(v));
}

// ---------------- fused prologue: embed | build_adj | ea repack | zero stats ----
__global__ void prologue_k(const float* __restrict__ x, const int* __restrict__ node_group,
                           const float* __restrict__ gemb, const float* __restrict__ W,
                           const float* __restrict__ b,
                           const int* __restrict__ srcA, const int* __restrict__ dst,
                           const float* __restrict__ ea) {
    int bid = blockIdx.x;
    int t = threadIdx.x;   // 256
    if (bid < PB_EMBED) {
        __shared__ float sx[16][132];
        int nb = bid * 16;
        for (int i = t; i < 16 * 132; i += 256) {
            int j = i / 132, c = i - j * 132;
            sx[j][c] = (c < 116) ? x[(nb + j) * 116 + c]
                                 : gemb[node_group[nb + j] * 16 + (c - 116)];
        }
        __syncthreads();
        int c = t & 63, jg = t >> 6;
        float bc = b[c];
        float a0 = bc, a1 = bc, a2 = bc, a3 = bc;
        #pragma unroll 4
        for (int r = 0; r < 132; r++) {
            float w = W[r * 64 + c];
            a0 += sx[jg][r] * w;
            a1 += sx[jg + 4][r] * w;
            a2 += sx[jg + 8][r] * w;
            a3 += sx[jg + 12][r] * w;
        }
        g_h0[(nb + jg) * 64 + c]      = a0 >= 0.f ? a0 : 0.01f * a0;
        g_h0[(nb + jg + 4) * 64 + c]  = a1 >= 0.f ? a1 : 0.01f * a1;
        g_h0[(nb + jg + 8) * 64 + c]  = a2 >= 0.f ? a2 : 0.01f * a2;
        g_h0[(nb + jg + 12) * 64 + c] = a3 >= 0.f ? a3 : 0.01f * a3;
    } else if (bid < PB_ADJ) {
        __shared__ int cnt[N_ROI];
        int g = bid - PB_EMBED;
        for (int i = t; i < N_ROI; i += 256) cnt[i] = 0;
        __syncthreads();
        int ebase = g * EPG, nbase = g * N_ROI;
        for (int e = t; e < EPG; e += 256) {
            int ge = ebase + e;
            int d = dst[ge] - nbase;
            int pos = atomicAdd(&cnt[d], 1);
            if (pos < MAXDEG) {
                int gn = nbase + d;
                g_nodelist[gn * MAXDEG + pos] = ge;
                g_srclist[gn * MAXDEG + pos] = srcA[ge];
            }
        }
        __syncthreads();
        for (int i = t; i < N_ROI; i += 256) g_deg[nbase + i] = min(cnt[i], MAXDEG);
    } else if (bid < PB_EA) {
        int e = (bid - PB_ADJ) * 256 + t;
        if (e < EE) {
            const float* a = ea + (long)e * 5;
            g_ea4[e] = make_float4(a[0], a[1], a[2], a[3]);
            g_ea1[e] = a[4];
        }
    } else {
        g_csum0[t] = 0.0; g_csq0[t] = 0.0;
        g_csum1[t] = 0.0; g_csq1[t] = 0.0;
    }
}

// ---------------- GINE aggregate + MLP + LayerNorm ----------------
__global__ void gine_k(const float* __restrict__ We, const float* __restrict__ be,
                       const float* __restrict__ W1, const float* __restrict__ b1,
                       const float* __restrict__ W2, const float* __restrict__ b2,
                       const float* __restrict__ lng, const float* __restrict__ lnb) {
    int n = blockIdx.x;
    int t = threadIdx.x;   // 64
    __shared__ float sh[64], sh2[64], ws[2], wq[2];
    float s = g_h0[n * 64 + t];
    int d = g_deg[n];
    const int* lst = g_nodelist + n * MAXDEG;
    const int* sl  = g_srclist  + n * MAXDEG;
    float bec = be[t];
    float w0 = We[t], w1 = We[64 + t], w2 = We[128 + t], w3 = We[192 + t], w4 = We[256 + t];
    int i0 = 0;
    for (; i0 + 4 <= d; i0 += 4) {
        int4 ev = *(const int4*)(lst + i0);
        int4 sv = *(const int4*)(sl + i0);
        float  hv0 = g_h0[sv.x * 64 + t], hv1 = g_h0[sv.y * 64 + t];
        float  hv2 = g_h0[sv.z * 64 + t], hv3 = g_h0[sv.w * 64 + t];
        float4 a0 = g_ea4[ev.x]; float a0e = g_ea1[ev.x];
        float4 a1 = g_ea4[ev.y]; float a1e = g_ea1[ev.y];
        float4 a2 = g_ea4[ev.z]; float a2e = g_ea1[ev.z];
        float4 a3 = g_ea4[ev.w]; float a3e = g_ea1[ev.w];
        float em0 = bec + a0.x * w0 + a0.y * w1 + a0.z * w2 + a0.w * w3 + a0e * w4;
        float em1 = bec + a1.x * w0 + a1.y * w1 + a1.z * w2 + a1.w * w3 + a1e * w4;
        float em2 = bec + a2.x * w0 + a2.y * w1 + a2.z * w2 + a2.w * w3 + a2e * w4;
        float em3 = bec + a3.x * w0 + a3.y * w1 + a3.z * w2 + a3.w * w3 + a3e * w4;
        em0 = em0 >= 0.f ? em0 : 0.01f * em0;
        em1 = em1 >= 0.f ? em1 : 0.01f * em1;
        em2 = em2 >= 0.f ? em2 : 0.01f * em2;
        em3 = em3 >= 0.f ? em3 : 0.01f * em3;
        float v0 = hv0 + em0, v1 = hv1 + em1, v2 = hv2 + em2, v3 = hv3 + em3;
        s += (v0 > 0.f ? v0 : 0.f) + (v1 > 0.f ? v1 : 0.f)
           + (v2 > 0.f ? v2 : 0.f) + (v3 > 0.f ? v3 : 0.f);
    }
    for (; i0 < d; i0++) {
        int e = lst[i0], src = sl[i0];
        float hv = g_h0[src * 64 + t];
        float4 a = g_ea4[e]; float ae = g_ea1[e];
        float em = bec + a.x * w0 + a.y * w1 + a.z * w2 + a.w * w3 + ae * w4;
        em = em >= 0.f ? em : 0.01f * em;
        float v = hv + em;
        s += v > 0.f ? v : 0.f;
    }
    sh[t] = s;
    __syncthreads();
    float acc = b1[t];
    #pragma unroll 8
    for (int r = 0; r < 64; r++) acc += sh[r] * W1[r * 64 + t];
    acc = acc >= 0.f ? acc : 0.01f * acc;
    sh2[t] = acc;
    __syncthreads();
    float acc2 = b2[t];
    #pragma unroll 8
    for (int r = 0; r < 64; r++) acc2 += sh2[r] * W2[r * 64 + t];
    acc2 = acc2 >= 0.f ? acc2 : 0.01f * acc2;
    float su = acc2, sq = acc2 * acc2;
    for (int o = 16; o; o >>= 1) {
        su += __shfl_down_sync(FULLMASK, su, o);
        sq += __shfl_down_sync(FULLMASK, sq, o);
    }
    if ((t & 31) == 0) { ws[t >> 5] = su; wq[t >> 5] = sq; }
    __syncthreads();
    float mu  = (ws[0] + ws[1]) * (1.f / 64.f);
    float var = (wq[0] + wq[1]) * (1.f / 64.f) - mu * mu;
    g_h1[n * 64 + t] = (acc2 - mu) * rsqrtf(var + 1e-5f) * lng[t] + lnb[t];
}

// ---------------- xlxr layer 0: 16 nodes/block, scalar ----------------
__global__ void xlxr0_k(const float* __restrict__ Wl, const float* __restrict__ Wr) {
    int nb = blockIdx.x * 16;
    int t = threadIdx.x;   // 256
    __shared__ float sh[16][HID];
    for (int i = t; i < 16 * 64; i += 256) {
        int j = i >> 6, c = i & 63;
        sh[j][c] = g_h1[(nb + j) * 64 + c];
    }
    __syncthreads();
    float al[16], ar[16];
    #pragma unroll
    for (int j = 0; j < 16; j++) { al[j] = 0.f; ar[j] = 0.f; }
    for (int r = 0; r < 64; r++) {
        float wl = Wl[r * 256 + t], wr = Wr[r * 256 + t];
        #pragma unroll
        for (int j = 0; j < 16; j++) {
            float hv = sh[j][r];
            al[j] += hv * wl;
            ar[j] += hv * wr;
        }
    }
    #pragma unroll
    for (int j = 0; j < 16; j++) {
        g_xl[(nb + j) * 256 + t] = al[j];
        g_xr[(nb + j) * 256 + t] = ar[j];
    }
}

// ---------------- xlxr layer 1: 16 nodes/block, f32x2, BN fused ----------------
__global__ void xlxr1_k(const float* __restrict__ Wl, const float* __restrict__ Wr,
                        const float* __restrict__ bng, const float* __restrict__ bnb) {
    int nb = blockIdx.x * 16;
    int t = threadIdx.x;   // 256
    __shared__ unsigned long long sh2[16][HC];
    for (int i = t; i < 16 * 256; i += 256) {
        int j = i >> 8, c = i & 255;
        double mu_d  = g_csum0[c] * (1.0 / NN);
        double var_d = g_csq0[c] * (1.0 / NN) - mu_d * mu_d;
        float mu = (float)mu_d;
        float v = g_out[(nb + j) * 256 + c];
        v = (v - mu) * rsqrtf((float)var_d + 1e-5f) * bng[c] + bnb[c];
        v = v >= 0.f ? v : 0.01f * v;
        sh2[j][c] = pk2(v, v);
    }
    __syncthreads();
    unsigned long long acc[16];
    #pragma unroll
    for (int j = 0; j < 16; j++) acc[j] = 0ull;
    #pragma unroll 4
    for (int r = 0; r < 256; r++) {
        unsigned long long w2 = pk2(Wl[r * 256 + t], Wr[r * 256 + t]);
        #pragma unroll
        for (int j = 0; j < 16; j++) ffma2(acc[j], sh2[j][r], w2);
    }
    #pragma unroll
    for (int j = 0; j < 16; j++) {
        float lo, hi;
        unpk2(lo, hi, acc[j]);
        g_xl[(nb + j) * 256 + t] = lo;
        g_xr[(nb + j) * 256 + t] = hi;
    }
}

// ---------------- GATv2: 4 warps/node (2 chan-halves x 2 edge-halves) ----------
// Block = 256 threads = 2 nodes. Warp (w, eh) handles channels [w*128, w*128+128)
// over edges [eh half of list). No-max softmax => partials merge by addition.
__global__ void __launch_bounds__(256) gat_warp_k(
    const float* __restrict__ WeP,   // [5,256]
    const float* __restrict__ attF,  // [4*64]
    double* __restrict__ csum, double* __restrict__ csq)
{
    __shared__ float bsum[HC], bsq[HC];
    __shared__ float4 sacc[8][32];
    __shared__ float  ssml[8][32];
    int t = threadIdx.x, lane = t & 31, wid = t >> 5;
    for (int i = t; i < HC; i += 256) { bsum[i] = 0.f; bsq[i] = 0.f; }
    int nl = wid >> 2;              // node in block (0..1)
    int n  = blockIdx.x * 2 + nl;
    int w  = (wid >> 1) & 1;        // channel half
    int eh = wid & 1;               // edge half
    int c0 = w * 128 + lane * 4;
    float4 wp0 = *(const float4*)(WeP + c0);
    float4 wp1 = *(const float4*)(WeP + 256 + c0);
    float4 wp2 = *(const float4*)(WeP + 512 + c0);
    float4 wp3 = *(const float4*)(WeP + 768 + c0);
    float4 wp4 = *(const float4*)(WeP + 1024 + c0);
    float4 att = *(const float4*)(attF + c0);
    float4 xr  = *(const float4*)(g_xr + (long)n * 256 + c0);
    int d = g_deg[n];
    int dh = (d + 1) >> 1;
    int lo = eh ? dh : 0;
    int hi = eh ? d : dh;
    const int* lst = g_nodelist + n * MAXDEG;
    const int* sl  = g_srclist  + n * MAXDEG;
    float ssum = 0.f;
    float4 acc = make_float4(0.f, 0.f, 0.f, 0.f);
    __syncthreads();   // bsum/bsq init visible
    int i = lo;
    for (; i + 4 <= hi; i += 4) {
        int4 ev = *(const int4*)(lst + i);   // 16B-aligned only when i%4==0; lo may be odd
        // NOTE: use element loads to stay safe for unaligned lo
        int e0 = lst[i], e1 = lst[i + 1], e2 = lst[i + 2], e3 = lst[i + 3];
        int s0 = sl[i],  s1 = sl[i + 1],  s2 = sl[i + 2],  s3 = sl[i + 3];
        (void)ev;
        float4 x0 = *(const float4*)(g_xl + (long)s0 * 256 + c0);
        float4 x1 = *(const float4*)(g_xl + (long)s1 * 256 + c0);
        float4 x2 = *(const float4*)(g_xl + (long)s2 * 256 + c0);
        float4 x3 = *(const float4*)(g_xl + (long)s3 * 256 + c0);
        float4 a40 = g_ea4[e0]; float a10 = g_ea1[e0];
        float4 a41 = g_ea4[e1]; float a11 = g_ea1[e1];
        float4 a42 = g_ea4[e2]; float a12 = g_ea1[e2];
        float4 a43 = g_ea4[e3]; float a13 = g_ea1[e3];
        float p0, p1, p2, p3;
        {
            float zx = x0.x + xr.x + a40.x*wp0.x + a40.y*wp1.x + a40.z*wp2.x + a40.w*wp3.x + a10*wp4.x;
            float zy = x0.y + xr.y + a40.x*wp0.y + a40.y*wp1.y + a40.z*wp2.y + a40.w*wp3.y + a10*wp4.y;
            float zz = x0.z + xr.z + a40.x*wp0.z + a40.y*wp1.z + a40.z*wp2.z + a40.w*wp3.z + a10*wp4.z;
            float zw = x0.w + xr.w + a40.x*wp0.w + a40.y*wp1.w + a40.z*wp2.w + a40.w*wp3.w + a10*wp4.w;
            zx = fmaxf(zx, 0.2f * zx); zy = fmaxf(zy, 0.2f * zy);
            zz = fmaxf(zz, 0.2f * zz); zw = fmaxf(zw, 0.2f * zw);
            p0 = zx*att.x + zy*att.y + zz*att.z + zw*att.w;
        }
        {
            float zx = x1.x + xr.x + a41.x*wp0.x + a41.y*wp1.x + a41.z*wp2.x + a41.w*wp3.x + a11*wp4.x;
            float zy = x1.y + xr.y + a41.x*wp0.y + a41.y*wp1.y + a41.z*wp2.y + a41.w*wp3.y + a11*wp4.y;
            float zz = x1.z + xr.z + a41.x*wp0.z + a41.y*wp1.z + a41.z*wp2.z + a41.w*wp3.z + a11*wp4.z;
            float zw = x1.w + xr.w + a41.x*wp0.w + a41.y*wp1.w + a41.z*wp2.w + a41.w*wp3.w + a11*wp4.w;
            zx = fmaxf(zx, 0.2f * zx); zy = fmaxf(zy, 0.2f * zy);
            zz = fmaxf(zz, 0.2f * zz); zw = fmaxf(zw, 0.2f * zw);
            p1 = zx*att.x + zy*att.y + zz*att.z + zw*att.w;
        }
        {
            float zx = x2.x + xr.x + a42.x*wp0.x + a42.y*wp1.x + a42.z*wp2.x + a42.w*wp3.x + a12*wp4.x;
            float zy = x2.y + xr.y + a42.x*wp0.y + a42.y*wp1.y + a42.z*wp2.y + a42.w*wp3.y + a12*wp4.y;
            float zz = x2.z + xr.z + a42.x*wp0.z + a42.y*wp1.z + a42.z*wp2.z + a42.w*wp3.z + a12*wp4.z;
            float zw = x2.w + xr.w + a42.x*wp0.w + a42.y*wp1.w + a42.z*wp2.w + a42.w*wp3.w + a12*wp4.w;
            zx = fmaxf(zx, 0.2f * zx); zy = fmaxf(zy, 0.2f * zy);
            zz = fmaxf(zz, 0.2f * zz); zw = fmaxf(zw, 0.2f * zw);
            p2 = zx*att.x + zy*att.y + zz*att.z + zw*att.w;
        }
        {
            float zx = x3.x + xr.x + a43.x*wp0.x + a43.y*wp1.x + a43.z*wp2.x + a43.w*wp3.x + a13*wp4.x;
            float zy = x3.y + xr.y + a43.x*wp0.y + a43.y*wp1.y + a43.z*wp2.y + a43.w*wp3.y + a13*wp4.y;
            float zz = x3.z + xr.z + a43.x*wp0.z + a43.y*wp1.z + a43.z*wp2.z + a43.w*wp3.z + a13*wp4.z;
            float zw = x3.w + xr.w + a43.x*wp0.w + a43.y*wp1.w + a43.z*wp2.w + a43.w*wp3.w + a13*wp4.w;
            zx = fmaxf(zx, 0.2f * zx); zy = fmaxf(zy, 0.2f * zy);
            zz = fmaxf(zz, 0.2f * zz); zw = fmaxf(zw, 0.2f * zw);
            p3 = zx*att.x + zy*att.y + zz*att.z + zw*att.w;
        }
        #pragma unroll
        for (int o = 8; o; o >>= 1) {
            p0 += __shfl_xor_sync(FULLMASK, p0, o);
            p1 += __shfl_xor_sync(FULLMASK, p1, o);
            p2 += __shfl_xor_sync(FULLMASK, p2, o);
            p3 += __shfl_xor_sync(FULLMASK, p3, o);
        }
        float w0 = __expf(p0), w1 = __expf(p1), w2 = __expf(p2), w3 = __expf(p3);
        ssum += (w0 + w1) + (w2 + w3);
        acc.x += (w0*x0.x + w1*x1.x) + (w2*x2.x + w3*x3.x);
        acc.y += (w0*x0.y + w1*x1.y) + (w2*x2.y + w3*x3.y);
        acc.z += (w0*x0.z + w1*x1.z) + (w2*x2.z + w3*x3.z);
        acc.w += (w0*x0.w + w1*x1.w) + (w2*x2.w + w3*x3.w);
    }
    for (; i < hi; i++) {
        int e = lst[i], s0 = sl[i];
        float4 x0 = *(const float4*)(g_xl + (long)s0 * 256 + c0);
        float4 a4 = g_ea4[e]; float a1e = g_ea1[e];
        float zx = x0.x + xr.x + a4.x*wp0.x + a4.y*wp1.x + a4.z*wp2.x + a4.w*wp3.x + a1e*wp4.x;
        float zy = x0.y + xr.y + a4.x*wp0.y + a4.y*wp1.y + a4.z*wp2.y + a4.w*wp3.y + a1e*wp4.y;
        float zz = x0.z + xr.z + a4.x*wp0.z + a4.y*wp1.z + a4.z*wp2.z + a4.w*wp3.z + a1e*wp4.z;
        float zw = x0.w + xr.w + a4.x*wp0.w + a4.y*wp1.w + a4.z*wp2.w + a4.w*wp3.w + a1e*wp4.w;
        zx = fmaxf(zx, 0.2f * zx); zy = fmaxf(zy, 0.2f * zy);
        zz = fmaxf(zz, 0.2f * zz); zw = fmaxf(zw, 0.2f * zw);
        float p0 = zx*att.x + zy*att.y + zz*att.z + zw*att.w;
        #pragma unroll
        for (int o = 8; o; o >>= 1) p0 += __shfl_xor_sync(FULLMASK, p0, o);
        float w0 = __expf(p0);
        ssum += w0;
        acc.x += w0 * x0.x;
        acc.y += w0 * x0.y;
        acc.z += w0 * x0.z;
        acc.w += w0 * x0.w;
    }
    sacc[wid][lane] = acc;
    ssml[wid][lane] = ssum;
    __syncthreads();
    if (eh == 0) {
        float4 a2 = sacc[wid + 1][lane];
        float  s2 = ssml[wid + 1][lane];
        acc.x += a2.x; acc.y += a2.y; acc.z += a2.z; acc.w += a2.w;
        ssum += s2;
        float inv = 1.f / (ssum + 1e-16f);
        float4 o4 = make_float4(acc.x * inv, acc.y * inv, acc.z * inv, acc.w * inv);
        *(float4*)(g_out + (long)n * 256 + c0) = o4;
        atomicAdd(&bsum[c0],     o4.x); atomicAdd(&bsq[c0],     o4.x * o4.x);
        atomicAdd(&bsum[c0 + 1], o4.y); atomicAdd(&bsq[c0 + 1], o4.y * o4.y);
        atomicAdd(&bsum[c0 + 2], o4.z); atomicAdd(&bsq[c0 + 2], o4.z * o4.z);
        atomicAdd(&bsum[c0 + 3], o4.w); atomicAdd(&bsq[c0 + 3], o4.w * o4.w);
    }
    __syncthreads();
    if (t < HC) {
        atomicAdd(&csum[t], (double)bsum[t]);
        atomicAdd(&csq[t],  (double)bsq[t]);
    }
}

// ---------------- pool + classifier (BN+leaky of layer 1 fused in) -------------
__global__ void pool_k(const float* __restrict__ W, const float* __restrict__ bb,
                       const float* __restrict__ gam, const float* __restrict__ bet,
                       float* __restrict__ outp) {
    int g = blockIdx.x;
    int t = threadIdx.x;  // 256 = channel
    double mu_d  = g_csum1[t] * (1.0 / NN);
    double var_d = g_csq1[t] * (1.0 / NN) - mu_d * mu_d;
    float mu = (float)mu_d;
    float rs = rsqrtf((float)var_d + 1e-5f) * gam[t];
    float bt = bet[t];
    float s = 0.f;
    int base = g * N_ROI;
    for (int r = 0; r < N_ROI; r++) {
        float v = g_out[(base + r) * 256 + t];
        v = (v - mu) * rs + bt;
        v = v >= 0.f ? v : 0.01f * v;
        s += v;
    }
    s *= (1.f / (float)N_ROI);
    float c0 = s * W[t * 2], c1 = s * W[t * 2 + 1];
    __shared__ float r0s[8], r1s[8];
    for (int o = 16; o; o >>= 1) {
        c0 += __shfl_down_sync(FULLMASK, c0, o);
        c1 += __shfl_down_sync(FULLMASK, c1, o);
    }
    if ((t & 31) == 0) { r0s[t >> 5] = c0; r1s[t >> 5] = c1; }
    __syncthreads();
    if (t == 0) {
        float a = 0.f, b2 = 0.f;
        for (int i = 0; i < 8; i++) { a += r0s[i]; b2 += r1s[i]; }
        outp[g * 2]     = a  + bb[0];
        outp[g * 2 + 1] = b2 + bb[1];
    }
}

// ---------------- launch --------------------------------------------------------
extern "C" void kernel_launch(void* const* d_in, const int* in_sizes, int n_in,
                              void* d_out, int out_size) {
    const float* x          = (const float*)d_in[0];
    const int*   edge_index = (const int*)  d_in[1];
    const float* edge_attr  = (const float*)d_in[2];
    const int*   node_group = (const int*)  d_in[4];
    const float* group_emb  = (const float*)d_in[5];
    const float* W_embed    = (const float*)d_in[6];
    const float* b_embed    = (const float*)d_in[7];
    const float* We_enc     = (const float*)d_in[8];
    const float* be_enc     = (const float*)d_in[9];
    const float* W1         = (const float*)d_in[10];
    const float* b1         = (const float*)d_in[11];
    const float* W2         = (const float*)d_in[12];
    const float* b2         = (const float*)d_in[13];
    const float* ln_g       = (const float*)d_in[14];
    const float* ln_b       = (const float*)d_in[15];
    const float* l0_Wl      = (const float*)d_in[16];
    const float* l0_Wr      = (const float*)d_in[17];
    const float* l0_We      = (const float*)d_in[18];
    const float* l0_att     = (const float*)d_in[19];
    const float* l0_bn_g    = (const float*)d_in[21];
    const float* l0_bn_b    = (const float*)d_in[22];
    const float* l1_Wl      = (const float*)d_in[23];
    const float* l1_Wr      = (const float*)d_in[24];
    const float* l1_We      = (const float*)d_in[25];
    const float* l1_att     = (const float*)d_in[26];
    const float* l1_bn_g    = (const float*)d_in[28];
    const float* l1_bn_b    = (const float*)d_in[29];
    const float* fc2_W      = (const float*)d_in[30];
    const float* fc2_b      = (const float*)d_in[31];

    const int* srcp = edge_index;
    const int* dstp = edge_index + EE;

    double* csum0; double* csq0; double* csum1; double* csq1;
    cudaGetSymbolAddress((void**)&csum0, g_csum0);
    cudaGetSymbolAddress((void**)&csq0,  g_csq0);
    cudaGetSymbolAddress((void**)&csum1, g_csum1);
    cudaGetSymbolAddress((void**)&csq1,  g_csq1);

    prologue_k<<<PB_TOTAL, 256>>>(x, node_group, group_emb, W_embed, b_embed,
                                  srcp, dstp, edge_attr);
    gine_k<<<NN, 64>>>(We_enc, be_enc, W1, b1, W2, b2, ln_g, ln_b);
    xlxr0_k<<<NN / 16, 256>>>(l0_Wl, l0_Wr);
    // 4 (profiled): GAT layer 0
    gat_warp_k<<<NN / 2, 256>>>(l0_We, l0_att, csum0, csq0);
    xlxr1_k<<<NN / 16, 256>>>(l1_Wl, l1_Wr, l0_bn_g, l0_bn_b);
    gat_warp_k<<<NN / 2, 256>>>(l1_We, l1_att, csum1, csq1);
    pool_k<<<G, 256>>>(fc2_W, fc2_b, l1_bn_g, l1_bn_b, (float*)d_out);
}

// round 14
// speedup vs baseline: 1.0340x; 1.0340x over previous
#include <cuda_runtime.h>
#include <cuda_bf16.h>
#include <math.h>

#define FULLMASK 0xffffffffu

static const int N_ROI = 116;
static const int G     = 128;
static const int DEG   = 32;
static const int NN    = G * N_ROI;        // 14848 nodes
static const int EE    = G * N_ROI * DEG;  // 475136 edges
static const int EPG   = N_ROI * DEG;      // 3712 edges per graph
static const int HID   = 64;
static const int HC    = 256;
static const int MAXDEG = 192;

// grid partition for the fused prologue
static const int PB_EMBED = NN / 16;            // 928
static const int PB_ADJ   = PB_EMBED + G;       // 1056
static const int PB_EA    = PB_ADJ + EE / 256;  // 2912
static const int PB_TOTAL = PB_EA + 1;          // 2913

// ---------------- device scratch (allocation-free) ----------------
__device__ float  g_h0[NN * HID];
__device__ float  g_h1[NN * HID];
__device__ float  g_xl[NN * HC];
__device__ float  g_xr[NN * HC];
__device__ float  g_out[NN * HC];
__device__ int    g_nodelist[NN * MAXDEG];
__device__ int    g_srclist[NN * MAXDEG];
__device__ int    g_deg[NN];
__device__ float4 g_ea4[EE];
__device__ float  g_ea1[EE];
__device__ double g_csum0[HC];
__device__ double g_csq0[HC];
__device__ double g_csum1[HC];
__device__ double g_csq1[HC];

// ---------------- f32x2 packed-FMA helpers (Blackwell) ----------------
__device__ __forceinline__ unsigned long long pk2(float lo, float hi) {
    unsigned long long r;
    asm("mov.b64 %0, {%1, %2};" : "=l"(r) : "f"(lo), "f"(hi));
    return r;
}
__device__ __forceinline__ void ffma2(unsigned long long& d, unsigned long long a,
                                      unsigned long long b) {
    asm("fma.rn.f32x2 %0, %1, %2, %0;" : "+l"(d) : "l"(a), "l"(b));
}
__device__ __forceinline__ void unpk2(float& lo, float& hi, unsigned long long v) {
    asm("mov.b64 {%0, %1}, %2;" : "=f"(lo), "=f"(hi) : "l"(v));
}

// ---------------- fused prologue: embed | build_adj | ea repack | zero stats ----
__global__ void prologue_k(const float* __restrict__ x, const int* __restrict__ node_group,
                           const float* __restrict__ gemb, const float* __restrict__ W,
                           const float* __restrict__ b,
                           const int* __restrict__ srcA, const int* __restrict__ dst,
                           const float* __restrict__ ea) {
    int bid = blockIdx.x;
    int t = threadIdx.x;   // 256
    if (bid < PB_EMBED) {
        __shared__ float sx[16][132];
        int nb = bid * 16;
        for (int i = t; i < 16 * 132; i += 256) {
            int j = i / 132, c = i - j * 132;
            sx[j][c] = (c < 116) ? x[(nb + j) * 116 + c]
                                 : gemb[node_group[nb + j] * 16 + (c - 116)];
        }
        __syncthreads();
        int c = t & 63, jg = t >> 6;
        float bc = b[c];
        float a0 = bc, a1 = bc, a2 = bc, a3 = bc;
        #pragma unroll 4
        for (int r = 0; r < 132; r++) {
            float w = W[r * 64 + c];
            a0 += sx[jg][r] * w;
            a1 += sx[jg + 4][r] * w;
            a2 += sx[jg + 8][r] * w;
            a3 += sx[jg + 12][r] * w;
        }
        g_h0[(nb + jg) * 64 + c]      = a0 >= 0.f ? a0 : 0.01f * a0;
        g_h0[(nb + jg + 4) * 64 + c]  = a1 >= 0.f ? a1 : 0.01f * a1;
        g_h0[(nb + jg + 8) * 64 + c]  = a2 >= 0.f ? a2 : 0.01f * a2;
        g_h0[(nb + jg + 12) * 64 + c] = a3 >= 0.f ? a3 : 0.01f * a3;
    } else if (bid < PB_ADJ) {
        __shared__ int cnt[N_ROI];
        int g = bid - PB_EMBED;
        for (int i = t; i < N_ROI; i += 256) cnt[i] = 0;
        __syncthreads();
        int ebase = g * EPG, nbase = g * N_ROI;
        for (int e = t; e < EPG; e += 256) {
            int ge = ebase + e;
            int d = dst[ge] - nbase;
            int pos = atomicAdd(&cnt[d], 1);
            if (pos < MAXDEG) {
                int gn = nbase + d;
                g_nodelist[gn * MAXDEG + pos] = ge;
                g_srclist[gn * MAXDEG + pos] = srcA[ge];
            }
        }
        __syncthreads();
        for (int i = t; i < N_ROI; i += 256) g_deg[nbase + i] = min(cnt[i], MAXDEG);
    } else if (bid < PB_EA) {
        int e = (bid - PB_ADJ) * 256 + t;
        if (e < EE) {
            const float* a = ea + (long)e * 5;
            g_ea4[e] = make_float4(a[0], a[1], a[2], a[3]);
            g_ea1[e] = a[4];
        }
    } else {
        g_csum0[t] = 0.0; g_csq0[t] = 0.0;
        g_csum1[t] = 0.0; g_csq1[t] = 0.0;
    }
}

// ---------------- GINE aggregate + MLP + LayerNorm ----------------
__global__ void gine_k(const float* __restrict__ We, const float* __restrict__ be,
                       const float* __restrict__ W1, const float* __restrict__ b1,
                       const float* __restrict__ W2, const float* __restrict__ b2,
                       const float* __restrict__ lng, const float* __restrict__ lnb) {
    int n = blockIdx.x;
    int t = threadIdx.x;   // 64
    __shared__ float sh[64], sh2[64], ws[2], wq[2];
    float s = g_h0[n * 64 + t];
    int d = g_deg[n];
    const int* lst = g_nodelist + n * MAXDEG;
    const int* sl  = g_srclist  + n * MAXDEG;
    float bec = be[t];
    float w0 = We[t], w1 = We[64 + t], w2 = We[128 + t], w3 = We[192 + t], w4 = We[256 + t];
    int i0 = 0;
    for (; i0 + 4 <= d; i0 += 4) {
        int4 ev = *(const int4*)(lst + i0);
        int4 sv = *(const int4*)(sl + i0);
        float  hv0 = g_h0[sv.x * 64 + t], hv1 = g_h0[sv.y * 64 + t];
        float  hv2 = g_h0[sv.z * 64 + t], hv3 = g_h0[sv.w * 64 + t];
        float4 a0 = g_ea4[ev.x]; float a0e = g_ea1[ev.x];
        float4 a1 = g_ea4[ev.y]; float a1e = g_ea1[ev.y];
        float4 a2 = g_ea4[ev.z]; float a2e = g_ea1[ev.z];
        float4 a3 = g_ea4[ev.w]; float a3e = g_ea1[ev.w];
        float em0 = bec + a0.x * w0 + a0.y * w1 + a0.z * w2 + a0.w * w3 + a0e * w4;
        float em1 = bec + a1.x * w0 + a1.y * w1 + a1.z * w2 + a1.w * w3 + a1e * w4;
        float em2 = bec + a2.x * w0 + a2.y * w1 + a2.z * w2 + a2.w * w3 + a2e * w4;
        float em3 = bec + a3.x * w0 + a3.y * w1 + a3.z * w2 + a3.w * w3 + a3e * w4;
        em0 = em0 >= 0.f ? em0 : 0.01f * em0;
        em1 = em1 >= 0.f ? em1 : 0.01f * em1;
        em2 = em2 >= 0.f ? em2 : 0.01f * em2;
        em3 = em3 >= 0.f ? em3 : 0.01f * em3;
        float v0 = hv0 + em0, v1 = hv1 + em1, v2 = hv2 + em2, v3 = hv3 + em3;
        s += (v0 > 0.f ? v0 : 0.f) + (v1 > 0.f ? v1 : 0.f)
           + (v2 > 0.f ? v2 : 0.f) + (v3 > 0.f ? v3 : 0.f);
    }
    for (; i0 < d; i0++) {
        int e = lst[i0], src = sl[i0];
        float hv = g_h0[src * 64 + t];
        float4 a = g_ea4[e]; float ae = g_ea1[e];
        float em = bec + a.x * w0 + a.y * w1 + a.z * w2 + a.w * w3 + ae * w4;
        em = em >= 0.f ? em : 0.01f * em;
        float v = hv + em;
        s += v > 0.f ? v : 0.f;
    }
    sh[t] = s;
    __syncthreads();
    float acc = b1[t];
    #pragma unroll 8
    for (int r = 0; r < 64; r++) acc += sh[r] * W1[r * 64 + t];
    acc = acc >= 0.f ? acc : 0.01f * acc;
    sh2[t] = acc;
    __syncthreads();
    float acc2 = b2[t];
    #pragma unroll 8
    for (int r = 0; r < 64; r++) acc2 += sh2[r] * W2[r * 64 + t];
    acc2 = acc2 >= 0.f ? acc2 : 0.01f * acc2;
    float su = acc2, sq = acc2 * acc2;
    for (int o = 16; o; o >>= 1) {
        su += __shfl_down_sync(FULLMASK, su, o);
        sq += __shfl_down_sync(FULLMASK, sq, o);
    }
    if ((t & 31) == 0) { ws[t >> 5] = su; wq[t >> 5] = sq; }
    __syncthreads();
    float mu  = (ws[0] + ws[1]) * (1.f / 64.f);
    float var = (wq[0] + wq[1]) * (1.f / 64.f) - mu * mu;
    g_h1[n * 64 + t] = (acc2 - mu) * rsqrtf(var + 1e-5f) * lng[t] + lnb[t];
}

// ---------------- xlxr layer 0: 16 nodes/block, scalar ----------------
__global__ void xlxr0_k(const float* __restrict__ Wl, const float* __restrict__ Wr) {
    int nb = blockIdx.x * 16;
    int t = threadIdx.x;   // 256
    __shared__ float sh[16][HID];
    for (int i = t; i < 16 * 64; i += 256) {
        int j = i >> 6, c = i & 63;
        sh[j][c] = g_h1[(nb + j) * 64 + c];
    }
    __syncthreads();
    float al[16], ar[16];
    #pragma unroll
    for (int j = 0; j < 16; j++) { al[j] = 0.f; ar[j] = 0.f; }
    for (int r = 0; r < 64; r++) {
        float wl = Wl[r * 256 + t], wr = Wr[r * 256 + t];
        #pragma unroll
        for (int j = 0; j < 16; j++) {
            float hv = sh[j][r];
            al[j] += hv * wl;
            ar[j] += hv * wr;
        }
    }
    #pragma unroll
    for (int j = 0; j < 16; j++) {
        g_xl[(nb + j) * 256 + t] = al[j];
        g_xr[(nb + j) * 256 + t] = ar[j];
    }
}

// ---------------- xlxr layer 1: 16 nodes/block, f32x2, BN fused ----------------
__global__ void xlxr1_k(const float* __restrict__ Wl, const float* __restrict__ Wr,
                        const float* __restrict__ bng, const float* __restrict__ bnb) {
    int nb = blockIdx.x * 16;
    int t = threadIdx.x;   // 256
    __shared__ unsigned long long sh2[16][HC];
    for (int i = t; i < 16 * 256; i += 256) {
        int j = i >> 8, c = i & 255;
        double mu_d  = g_csum0[c] * (1.0 / NN);
        double var_d = g_csq0[c] * (1.0 / NN) - mu_d * mu_d;
        float mu = (float)mu_d;
        float v = g_out[(nb + j) * 256 + c];
        v = (v - mu) * rsqrtf((float)var_d + 1e-5f) * bng[c] + bnb[c];
        v = v >= 0.f ? v : 0.01f * v;
        sh2[j][c] = pk2(v, v);
    }
    __syncthreads();
    unsigned long long acc[16];
    #pragma unroll
    for (int j = 0; j < 16; j++) acc[j] = 0ull;
    #pragma unroll 4
    for (int r = 0; r < 256; r++) {
        unsigned long long w2 = pk2(Wl[r * 256 + t], Wr[r * 256 + t]);
        #pragma unroll
        for (int j = 0; j < 16; j++) ffma2(acc[j], sh2[j][r], w2);
    }
    #pragma unroll
    for (int j = 0; j < 16; j++) {
        float lo, hi;
        unpk2(lo, hi, acc[j]);
        g_xl[(nb + j) * 256 + t] = lo;
        g_xr[(nb + j) * 256 + t] = hi;
    }
}

// ---------------- GATv2: R11 structure + register cap for 4 blocks/SM ----------
// 2 warps/node, 4 channels/lane, float4 gathers, online-max softmax.
__global__ void __launch_bounds__(256, 4) gat_warp_k(
    const float* __restrict__ WeP,   // [5,256]
    const float* __restrict__ attF,  // [4*64]
    double* __restrict__ csum, double* __restrict__ csq)
{
    __shared__ float bsum[HC], bsq[HC];
    int t = threadIdx.x, lane = t & 31, wid = t >> 5;
    for (int i = t; i < HC; i += 256) { bsum[i] = 0.f; bsq[i] = 0.f; }
    int n = blockIdx.x * 4 + (wid >> 1);
    int w = wid & 1;
    int c0 = w * 128 + lane * 4;
    float4 wp0 = *(const float4*)(WeP + c0);
    float4 wp1 = *(const float4*)(WeP + 256 + c0);
    float4 wp2 = *(const float4*)(WeP + 512 + c0);
    float4 wp3 = *(const float4*)(WeP + 768 + c0);
    float4 wp4 = *(const float4*)(WeP + 1024 + c0);
    float4 att = *(const float4*)(attF + c0);
    float4 xr  = *(const float4*)(g_xr + (long)n * 256 + c0);
    int d = g_deg[n];
    const int* lst = g_nodelist + n * MAXDEG;
    const int* sl  = g_srclist  + n * MAXDEG;
    float m = -1e30f, ssum = 0.f;
    float4 acc = make_float4(0.f, 0.f, 0.f, 0.f);
    __syncthreads();   // bsum/bsq init visible
    int i = 0;
    for (; i + 4 <= d; i += 4) {
        int4 ev = *(const int4*)(lst + i);
        int4 sv = *(const int4*)(sl + i);
        float4 x0 = *(const float4*)(g_xl + (long)sv.x * 256 + c0);
        float4 x1 = *(const float4*)(g_xl + (long)sv.y * 256 + c0);
        float4 x2 = *(const float4*)(g_xl + (long)sv.z * 256 + c0);
        float4 x3 = *(const float4*)(g_xl + (long)sv.w * 256 + c0);
        float4 a40 = g_ea4[ev.x]; float a10 = g_ea1[ev.x];
        float4 a41 = g_ea4[ev.y]; float a11 = g_ea1[ev.y];
        float4 a42 = g_ea4[ev.z]; float a12 = g_ea1[ev.z];
        float4 a43 = g_ea4[ev.w]; float a13 = g_ea1[ev.w];
        float p0, p1, p2, p3;
        {
            float zx = x0.x + xr.x + a40.x*wp0.x + a40.y*wp1.x + a40.z*wp2.x + a40.w*wp3.x + a10*wp4.x;
            float zy = x0.y + xr.y + a40.x*wp0.y + a40.y*wp1.y + a40.z*wp2.y + a40.w*wp3.y + a10*wp4.y;
            float zz = x0.z + xr.z + a40.x*wp0.z + a40.y*wp1.z + a40.z*wp2.z + a40.w*wp3.z + a10*wp4.z;
            float zw = x0.w + xr.w + a40.x*wp0.w + a40.y*wp1.w + a40.z*wp2.w + a40.w*wp3.w + a10*wp4.w;
            zx = zx >= 0.f ? zx : 0.2f * zx; zy = zy >= 0.f ? zy : 0.2f * zy;
            zz = zz >= 0.f ? zz : 0.2f * zz; zw = zw >= 0.f ? zw : 0.2f * zw;
            p0 = zx*att.x + zy*att.y + zz*att.z + zw*att.w;
        }
        {
            float zx = x1.x + xr.x + a41.x*wp0.x + a41.y*wp1.x + a41.z*wp2.x + a41.w*wp3.x + a11*wp4.x;
            float zy = x1.y + xr.y + a41.x*wp0.y + a41.y*wp1.y + a41.z*wp2.y + a41.w*wp3.y + a11*wp4.y;
            float zz = x1.z + xr.z + a41.x*wp0.z + a41.y*wp1.z + a41.z*wp2.z + a41.w*wp3.z + a11*wp4.z;
            float zw = x1.w + xr.w + a41.x*wp0.w + a41.y*wp1.w + a41.z*wp2.w + a41.w*wp3.w + a11*wp4.w;
            zx = zx >= 0.f ? zx : 0.2f * zx; zy = zy >= 0.f ? zy : 0.2f * zy;
            zz = zz >= 0.f ? zz : 0.2f * zz; zw = zw >= 0.f ? zw : 0.2f * zw;
            p1 = zx*att.x + zy*att.y + zz*att.z + zw*att.w;
        }
        {
            float zx = x2.x + xr.x + a42.x*wp0.x + a42.y*wp1.x + a42.z*wp2.x + a42.w*wp3.x + a12*wp4.x;
            float zy = x2.y + xr.y + a42.x*wp0.y + a42.y*wp1.y + a42.z*wp2.y + a42.w*wp3.y + a12*wp4.y;
            float zz = x2.z + xr.z + a42.x*wp0.z + a42.y*wp1.z + a42.z*wp2.z + a42.w*wp3.z + a12*wp4.z;
            float zw = x2.w + xr.w + a42.x*wp0.w + a42.y*wp1.w + a42.z*wp2.w + a42.w*wp3.w + a12*wp4.w;
            zx = zx >= 0.f ? zx : 0.2f * zx; zy = zy >= 0.f ? zy : 0.2f * zy;
            zz = zz >= 0.f ? zz : 0.2f * zz; zw = zw >= 0.f ? zw : 0.2f * zw;
            p2 = zx*att.x + zy*att.y + zz*att.z + zw*att.w;
        }
        {
            float zx = x3.x + xr.x + a43.x*wp0.x + a43.y*wp1.x + a43.z*wp2.x + a43.w*wp3.x + a13*wp4.x;
            float zy = x3.y + xr.y + a43.x*wp0.y + a43.y*wp1.y + a43.z*wp2.y + a43.w*wp3.y + a13*wp4.y;
            float zz = x3.z + xr.z + a43.x*wp0.z + a43.y*wp1.z + a43.z*wp2.z + a43.w*wp3.z + a13*wp4.z;
            float zw = x3.w + xr.w + a43.x*wp0.w + a43.y*wp1.w + a43.z*wp2.w + a43.w*wp3.w + a13*wp4.w;
            zx = zx >= 0.f ? zx : 0.2f * zx; zy = zy >= 0.f ? zy : 0.2f * zy;
            zz = zz >= 0.f ? zz : 0.2f * zz; zw = zw >= 0.f ? zw : 0.2f * zw;
            p3 = zx*att.x + zy*att.y + zz*att.z + zw*att.w;
        }
        #pragma unroll
        for (int o = 8; o; o >>= 1) {   // reduce within 16-lane half-warp (one head)
            p0 += __shfl_xor_sync(FULLMASK, p0, o);
            p1 += __shfl_xor_sync(FULLMASK, p1, o);
            p2 += __shfl_xor_sync(FULLMASK, p2, o);
            p3 += __shfl_xor_sync(FULLMASK, p3, o);
        }
        float mx = fmaxf(fmaxf(fmaxf(p0, p1), fmaxf(p2, p3)), m);
        float f  = __expf(m - mx);
        float w0 = __expf(p0 - mx), w1 = __expf(p1 - mx),
              w2 = __expf(p2 - mx), w3 = __expf(p3 - mx);
        ssum = ssum * f + ((w0 + w1) + (w2 + w3));
        acc.x = acc.x * f + ((w0*x0.x + w1*x1.x) + (w2*x2.x + w3*x3.x));
        acc.y = acc.y * f + ((w0*x0.y + w1*x1.y) + (w2*x2.y + w3*x3.y));
        acc.z = acc.z * f + ((w0*x0.z + w1*x1.z) + (w2*x2.z + w3*x3.z));
        acc.w = acc.w * f + ((w0*x0.w + w1*x1.w) + (w2*x2.w + w3*x3.w));
        m = mx;
    }
    for (; i < d; i++) {
        int e = lst[i], s0 = sl[i];
        float4 x0 = *(const float4*)(g_xl + (long)s0 * 256 + c0);
        float4 a4 = g_ea4[e]; float a1e = g_ea1[e];
        float zx = x0.x + xr.x + a4.x*wp0.x + a4.y*wp1.x + a4.z*wp2.x + a4.w*wp3.x + a1e*wp4.x;
        float zy = x0.y + xr.y + a4.x*wp0.y + a4.y*wp1.y + a4.z*wp2.y + a4.w*wp3.y + a1e*wp4.y;
        float zz = x0.z + xr.z + a4.x*wp0.z + a4.y*wp1.z + a4.z*wp2.z + a4.w*wp3.z + a1e*wp4.z;
        float zw = x0.w + xr.w + a4.x*wp0.w + a4.y*wp1.w + a4.z*wp2.w + a4.w*wp3.w + a1e*wp4.w;
        zx = zx >= 0.f ? zx : 0.2f * zx; zy = zy >= 0.f ? zy : 0.2f * zy;
        zz = zz >= 0.f ? zz : 0.2f * zz; zw = zw >= 0.f ? zw : 0.2f * zw;
        float p0 = zx*att.x + zy*att.y + zz*att.z + zw*att.w;
        #pragma unroll
        for (int o = 8; o; o >>= 1) p0 += __shfl_xor_sync(FULLMASK, p0, o);
        float mx = fmaxf(m, p0);
        float f = __expf(m - mx), w0 = __expf(p0 - mx);
        ssum = ssum * f + w0;
        acc.x = acc.x * f + w0 * x0.x;
        acc.y = acc.y * f + w0 * x0.y;
        acc.z = acc.z * f + w0 * x0.z;
        acc.w = acc.w * f + w0 * x0.w;
        m = mx;
    }
    float inv = 1.f / (ssum + 1e-16f);
    float4 o4 = make_float4(acc.x * inv, acc.y * inv, acc.z * inv, acc.w * inv);
    *(float4*)(g_out + (long)n * 256 + c0) = o4;
    atomicAdd(&bsum[c0],     o4.x); atomicAdd(&bsq[c0],     o4.x * o4.x);
    atomicAdd(&bsum[c0 + 1], o4.y); atomicAdd(&bsq[c0 + 1], o4.y * o4.y);
    atomicAdd(&bsum[c0 + 2], o4.z); atomicAdd(&bsq[c0 + 2], o4.z * o4.z);
    atomicAdd(&bsum[c0 + 3], o4.w); atomicAdd(&bsq[c0 + 3], o4.w * o4.w);
    __syncthreads();
    if (t < HC) {
        atomicAdd(&csum[t], (double)bsum[t]);
        atomicAdd(&csq[t],  (double)bsq[t]);
    }
}

// ---------------- pool + classifier (BN+leaky of layer 1 fused in) -------------
__global__ void pool_k(const float* __restrict__ W, const float* __restrict__ bb,
                       const float* __restrict__ gam, const float* __restrict__ bet,
                       float* __restrict__ outp) {
    int g = blockIdx.x;
    int t = threadIdx.x;  // 256 = channel
    double mu_d  = g_csum1[t] * (1.0 / NN);
    double var_d = g_csq1[t] * (1.0 / NN) - mu_d * mu_d;
    float mu = (float)mu_d;
    float rs = rsqrtf((float)var_d + 1e-5f) * gam[t];
    float bt = bet[t];
    float s = 0.f;
    int base = g * N_ROI;
    for (int r = 0; r < N_ROI; r++) {
        float v = g_out[(base + r) * 256 + t];
        v = (v - mu) * rs + bt;
        v = v >= 0.f ? v : 0.01f * v;
        s += v;
    }
    s *= (1.f / (float)N_ROI);
    float c0 = s * W[t * 2], c1 = s * W[t * 2 + 1];
    __shared__ float r0s[8], r1s[8];
    for (int o = 16; o; o >>= 1) {
        c0 += __shfl_down_sync(FULLMASK, c0, o);
        c1 += __shfl_down_sync(FULLMASK, c1, o);
    }
    if ((t & 31) == 0) { r0s[t >> 5] = c0; r1s[t >> 5] = c1; }
    __syncthreads();
    if (t == 0) {
        float a = 0.f, b2 = 0.f;
        for (int i = 0; i < 8; i++) { a += r0s[i]; b2 += r1s[i]; }
        outp[g * 2]     = a  + bb[0];
        outp[g * 2 + 1] = b2 + bb[1];
    }
}

// ---------------- launch --------------------------------------------------------
extern "C" void kernel_launch(void* const* d_in, const int* in_sizes, int n_in,
                              void* d_out, int out_size) {
    const float* x          = (const float*)d_in[0];
    const int*   edge_index = (const int*)  d_in[1];
    const float* edge_attr  = (const float*)d_in[2];
    const int*   node_group = (const int*)  d_in[4];
    const float* group_emb  = (const float*)d_in[5];
    const float* W_embed    = (const float*)d_in[6];
    const float* b_embed    = (const float*)d_in[7];
    const float* We_enc     = (const float*)d_in[8];
    const float* be_enc     = (const float*)d_in[9];
    const float* W1         = (const float*)d_in[10];
    const float* b1         = (const float*)d_in[11];
    const float* W2         = (const float*)d_in[12];
    const float* b2         = (const float*)d_in[13];
    const float* ln_g       = (const float*)d_in[14];
    const float* ln_b       = (const float*)d_in[15];
    const float* l0_Wl      = (const float*)d_in[16];
    const float* l0_Wr      = (const float*)d_in[17];
    const float* l0_We      = (const float*)d_in[18];
    const float* l0_att     = (const float*)d_in[19];
    const float* l0_bn_g    = (const float*)d_in[21];
    const float* l0_bn_b    = (const float*)d_in[22];
    const float* l1_Wl      = (const float*)d_in[23];
    const float* l1_Wr      = (const float*)d_in[24];
    const float* l1_We      = (const float*)d_in[25];
    const float* l1_att     = (const float*)d_in[26];
    const float* l1_bn_g    = (const float*)d_in[28];
    const float* l1_bn_b    = (const float*)d_in[29];
    const float* fc2_W      = (const float*)d_in[30];
    const float* fc2_b      = (const float*)d_in[31];

    const int* srcp = edge_index;
    const int* dstp = edge_index + EE;

    double* csum0; double* csq0; double* csum1; double* csq1;
    cudaGetSymbolAddress((void**)&csum0, g_csum0);
    cudaGetSymbolAddress((void**)&csq0,  g_csq0);
    cudaGetSymbolAddress((void**)&csum1, g_csum1);
    cudaGetSymbolAddress((void**)&csq1,  g_csq1);

    prologue_k<<<PB_TOTAL, 256>>>(x, node_group, group_emb, W_embed, b_embed,
                                  srcp, dstp, edge_attr);
    gine_k<<<NN, 64>>>(We_enc, be_enc, W1, b1, W2, b2, ln_g, ln_b);
    xlxr0_k<<<NN / 16, 256>>>(l0_Wl, l0_Wr);
    // 4 (profiled): GAT layer 0
    gat_warp_k<<<NN / 4, 256>>>(l0_We, l0_att, csum0, csq0);
    xlxr1_k<<<NN / 16, 256>>>(l1_Wl, l1_Wr, l0_bn_g, l0_bn_b);
    gat_warp_k<<<NN / 4, 256>>>(l1_We, l1_att, csum1, csq1);
    pool_k<<<G, 256>>>(fc2_W, fc2_b, l1_bn_g, l1_bn_b, (float*)d_out);
}

// round 15
// speedup vs baseline: 1.1270x; 1.0900x over previous
#include <cuda_runtime.h>
#include <cuda_bf16.h>
#include <math.h>

#define FULLMASK 0xffffffffu

static const int N_ROI = 116;
static const int G     = 128;
static const int DEG   = 32;
static const int NN    = G * N_ROI;        // 14848 nodes
static const int EE    = G * N_ROI * DEG;  // 475136 edges
static const int EPG   = N_ROI * DEG;      // 3712 edges per graph
static const int HID   = 64;
static const int HC    = 256;
static const int MAXDEG = 192;

// grid partition for the fused prologue
static const int PB_EMBED = NN / 16;            // 928
static const int PB_ADJ   = PB_EMBED + G;       // 1056
static const int PB_EA    = PB_ADJ + EE / 256;  // 2912
static const int PB_TOTAL = PB_EA + 1;          // 2913

// ---------------- device scratch (allocation-free) ----------------
__device__ float  g_h0[NN * HID];
__device__ float  g_h1[NN * HID];
__device__ float  g_xl[NN * HC];
__device__ float  g_xr[NN * HC];
__device__ float  g_out[NN * HC];
__device__ int    g_nodelist[NN * MAXDEG];
__device__ int    g_srclist[NN * MAXDEG];
__device__ int    g_deg[NN];
__device__ float4 g_ea4[EE];
__device__ float  g_ea1[EE];
__device__ double g_csum0[HC];
__device__ double g_csq0[HC];
__device__ double g_csum1[HC];
__device__ double g_csq1[HC];

typedef unsigned long long ull;

// ---------------- f32x2 packed helpers (Blackwell) ----------------
__device__ __forceinline__ ull pk2(float lo, float hi) {
    ull r;
    asm("mov.b64 %0, {%1, %2};" : "=l"(r) : "f"(lo), "f"(hi));
    return r;
}
__device__ __forceinline__ void ffma2(ull& d, ull a, ull b) {
    asm("fma.rn.f32x2 %0, %1, %2, %0;" : "+l"(d) : "l"(a), "l"(b));
}
__device__ __forceinline__ ull fma2_(ull a, ull b, ull c) {
    ull d;
    asm("fma.rn.f32x2 %0, %1, %2, %3;" : "=l"(d) : "l"(a), "l"(b), "l"(c));
    return d;
}
__device__ __forceinline__ ull add2_(ull a, ull b) {
    ull d;
    asm("add.rn.f32x2 %0, %1, %2;" : "=l"(d) : "l"(a), "l"(b));
    return d;
}
__device__ __forceinline__ ull mul2_(ull a, ull b) {
    ull d;
    asm("mul.rn.f32x2 %0, %1, %2;" : "=l"(d) : "l"(a), "l"(b));
    return d;
}
__device__ __forceinline__ void unpk2(float& lo, float& hi, ull v) {
    asm("mov.b64 {%0, %1}, %2;" : "=f"(lo), "=f"(hi) : "l"(v));
}

// ---------------- fused prologue: embed | build_adj | ea repack | zero stats ----
__global__ void prologue_k(const float* __restrict__ x, const int* __restrict__ node_group,
                           const float* __restrict__ gemb, const float* __restrict__ W,
                           const float* __restrict__ b,
                           const int* __restrict__ srcA, const int* __restrict__ dst,
                           const float* __restrict__ ea) {
    int bid = blockIdx.x;
    int t = threadIdx.x;   // 256
    if (bid < PB_EMBED) {
        __shared__ float sx[16][132];
        int nb = bid * 16;
        for (int i = t; i < 16 * 132; i += 256) {
            int j = i / 132, c = i - j * 132;
            sx[j][c] = (c < 116) ? x[(nb + j) * 116 + c]
                                 : gemb[node_group[nb + j] * 16 + (c - 116)];
        }
        __syncthreads();
        int c = t & 63, jg = t >> 6;
        float bc = b[c];
        float a0 = bc, a1 = bc, a2 = bc, a3 = bc;
        #pragma unroll 4
        for (int r = 0; r < 132; r++) {
            float w = W[r * 64 + c];
            a0 += sx[jg][r] * w;
            a1 += sx[jg + 4][r] * w;
            a2 += sx[jg + 8][r] * w;
            a3 += sx[jg + 12][r] * w;
        }
        g_h0[(nb + jg) * 64 + c]      = a0 >= 0.f ? a0 : 0.01f * a0;
        g_h0[(nb + jg + 4) * 64 + c]  = a1 >= 0.f ? a1 : 0.01f * a1;
        g_h0[(nb + jg + 8) * 64 + c]  = a2 >= 0.f ? a2 : 0.01f * a2;
        g_h0[(nb + jg + 12) * 64 + c] = a3 >= 0.f ? a3 : 0.01f * a3;
    } else if (bid < PB_ADJ) {
        __shared__ int cnt[N_ROI];
        int g = bid - PB_EMBED;
        for (int i = t; i < N_ROI; i += 256) cnt[i] = 0;
        __syncthreads();
        int ebase = g * EPG, nbase = g * N_ROI;
        for (int e = t; e < EPG; e += 256) {
            int ge = ebase + e;
            int d = dst[ge] - nbase;
            int pos = atomicAdd(&cnt[d], 1);
            if (pos < MAXDEG) {
                int gn = nbase + d;
                g_nodelist[gn * MAXDEG + pos] = ge;
                g_srclist[gn * MAXDEG + pos] = srcA[ge];
            }
        }
        __syncthreads();
        for (int i = t; i < N_ROI; i += 256) g_deg[nbase + i] = min(cnt[i], MAXDEG);
    } else if (bid < PB_EA) {
        int e = (bid - PB_ADJ) * 256 + t;
        if (e < EE) {
            const float* a = ea + (long)e * 5;
            g_ea4[e] = make_float4(a[0], a[1], a[2], a[3]);
            g_ea1[e] = a[4];
        }
    } else {
        g_csum0[t] = 0.0; g_csq0[t] = 0.0;
        g_csum1[t] = 0.0; g_csq1[t] = 0.0;
    }
}

// ---------------- GINE aggregate + MLP + LayerNorm ----------------
__global__ void gine_k(const float* __restrict__ We, const float* __restrict__ be,
                       const float* __restrict__ W1, const float* __restrict__ b1,
                       const float* __restrict__ W2, const float* __restrict__ b2,
                       const float* __restrict__ lng, const float* __restrict__ lnb) {
    int n = blockIdx.x;
    int t = threadIdx.x;   // 64
    __shared__ float sh[64], sh2[64], ws[2], wq[2];
    float s = g_h0[n * 64 + t];
    int d = g_deg[n];
    const int* lst = g_nodelist + n * MAXDEG;
    const int* sl  = g_srclist  + n * MAXDEG;
    float bec = be[t];
    float w0 = We[t], w1 = We[64 + t], w2 = We[128 + t], w3 = We[192 + t], w4 = We[256 + t];
    int i0 = 0;
    for (; i0 + 4 <= d; i0 += 4) {
        int4 ev = *(const int4*)(lst + i0);
        int4 sv = *(const int4*)(sl + i0);
        float  hv0 = g_h0[sv.x * 64 + t], hv1 = g_h0[sv.y * 64 + t];
        float  hv2 = g_h0[sv.z * 64 + t], hv3 = g_h0[sv.w * 64 + t];
        float4 a0 = g_ea4[ev.x]; float a0e = g_ea1[ev.x];
        float4 a1 = g_ea4[ev.y]; float a1e = g_ea1[ev.y];
        float4 a2 = g_ea4[ev.z]; float a2e = g_ea1[ev.z];
        float4 a3 = g_ea4[ev.w]; float a3e = g_ea1[ev.w];
        float em0 = bec + a0.x * w0 + a0.y * w1 + a0.z * w2 + a0.w * w3 + a0e * w4;
        float em1 = bec + a1.x * w0 + a1.y * w1 + a1.z * w2 + a1.w * w3 + a1e * w4;
        float em2 = bec + a2.x * w0 + a2.y * w1 + a2.z * w2 + a2.w * w3 + a2e * w4;
        float em3 = bec + a3.x * w0 + a3.y * w1 + a3.z * w2 + a3.w * w3 + a3e * w4;
        em0 = em0 >= 0.f ? em0 : 0.01f * em0;
        em1 = em1 >= 0.f ? em1 : 0.01f * em1;
        em2 = em2 >= 0.f ? em2 : 0.01f * em2;
        em3 = em3 >= 0.f ? em3 : 0.01f * em3;
        float v0 = hv0 + em0, v1 = hv1 + em1, v2 = hv2 + em2, v3 = hv3 + em3;
        s += (v0 > 0.f ? v0 : 0.f) + (v1 > 0.f ? v1 : 0.f)
           + (v2 > 0.f ? v2 : 0.f) + (v3 > 0.f ? v3 : 0.f);
    }
    for (; i0 < d; i0++) {
        int e = lst[i0], src = sl[i0];
        float hv = g_h0[src * 64 + t];
        float4 a = g_ea4[e]; float ae = g_ea1[e];
        float em = bec + a.x * w0 + a.y * w1 + a.z * w2 + a.w * w3 + ae * w4;
        em = em >= 0.f ? em : 0.01f * em;
        float v = hv + em;
        s += v > 0.f ? v : 0.f;
    }
    sh[t] = s;
    __syncthreads();
    float acc = b1[t];
    #pragma unroll 8
    for (int r = 0; r < 64; r++) acc += sh[r] * W1[r * 64 + t];
    acc = acc >= 0.f ? acc : 0.01f * acc;
    sh2[t] = acc;
    __syncthreads();
    float acc2 = b2[t];
    #pragma unroll 8
    for (int r = 0; r < 64; r++) acc2 += sh2[r] * W2[r * 64 + t];
    acc2 = acc2 >= 0.f ? acc2 : 0.01f * acc2;
    float su = acc2, sq = acc2 * acc2;
    for (int o = 16; o; o >>= 1) {
        su += __shfl_down_sync(FULLMASK, su, o);
        sq += __shfl_down_sync(FULLMASK, sq, o);
    }
    if ((t & 31) == 0) { ws[t >> 5] = su; wq[t >> 5] = sq; }
    __syncthreads();
    float mu  = (ws[0] + ws[1]) * (1.f / 64.f);
    float var = (wq[0] + wq[1]) * (1.f / 64.f) - mu * mu;
    g_h1[n * 64 + t] = (acc2 - mu) * rsqrtf(var + 1e-5f) * lng[t] + lnb[t];
}

// ---------------- xlxr layer 0: 16 nodes/block, scalar ----------------
__global__ void xlxr0_k(const float* __restrict__ Wl, const float* __restrict__ Wr) {
    int nb = blockIdx.x * 16;
    int t = threadIdx.x;   // 256
    __shared__ float sh[16][HID];
    for (int i = t; i < 16 * 64; i += 256) {
        int j = i >> 6, c = i & 63;
        sh[j][c] = g_h1[(nb + j) * 64 + c];
    }
    __syncthreads();
    float al[16], ar[16];
    #pragma unroll
    for (int j = 0; j < 16; j++) { al[j] = 0.f; ar[j] = 0.f; }
    for (int r = 0; r < 64; r++) {
        float wl = Wl[r * 256 + t], wr = Wr[r * 256 + t];
        #pragma unroll
        for (int j = 0; j < 16; j++) {
            float hv = sh[j][r];
            al[j] += hv * wl;
            ar[j] += hv * wr;
        }
    }
    #pragma unroll
    for (int j = 0; j < 16; j++) {
        g_xl[(nb + j) * 256 + t] = al[j];
        g_xr[(nb + j) * 256 + t] = ar[j];
    }
}

// ---------------- xlxr layer 1: 16 nodes/block, f32x2, BN fused ----------------
__global__ void xlxr1_k(const float* __restrict__ Wl, const float* __restrict__ Wr,
                        const float* __restrict__ bng, const float* __restrict__ bnb) {
    int nb = blockIdx.x * 16;
    int t = threadIdx.x;   // 256
    __shared__ ull sh2[16][HC];
    for (int i = t; i < 16 * 256; i += 256) {
        int j = i >> 8, c = i & 255;
        double mu_d  = g_csum0[c] * (1.0 / NN);
        double var_d = g_csq0[c] * (1.0 / NN) - mu_d * mu_d;
        float mu = (float)mu_d;
        float v = g_out[(nb + j) * 256 + c];
        v = (v - mu) * rsqrtf((float)var_d + 1e-5f) * bng[c] + bnb[c];
        v = v >= 0.f ? v : 0.01f * v;
        sh2[j][c] = pk2(v, v);
    }
    __syncthreads();
    ull acc[16];
    #pragma unroll
    for (int j = 0; j < 16; j++) acc[j] = 0ull;
    #pragma unroll 4
    for (int r = 0; r < 256; r++) {
        ull w2 = pk2(Wl[r * 256 + t], Wr[r * 256 + t]);
        #pragma unroll
        for (int j = 0; j < 16; j++) ffma2(acc[j], sh2[j][r], w2);
    }
    #pragma unroll
    for (int j = 0; j < 16; j++) {
        float lo, hi;
        unpk2(lo, hi, acc[j]);
        g_xl[(nb + j) * 256 + t] = lo;
        g_xr[(nb + j) * 256 + t] = hi;
    }
}

// ---------------- GATv2: R11 structure, packed f32x2 inner math ----------------
// 2 warps/node, 4 channels/lane as 2 packed pairs; online-max softmax.
// leaky(z) = 0.6z + 0.4|z| (exact identity for slope 0.2).
__global__ void __launch_bounds__(256, 3) gat_warp_k(
    const float* __restrict__ WeP,   // [5,256]
    const float* __restrict__ attF,  // [4*64]
    double* __restrict__ csum, double* __restrict__ csq)
{
    __shared__ float bsum[HC], bsq[HC];
    int t = threadIdx.x, lane = t & 31, wid = t >> 5;
    for (int i = t; i < HC; i += 256) { bsum[i] = 0.f; bsq[i] = 0.f; }
    int n = blockIdx.x * 4 + (wid >> 1);
    int w = wid & 1;
    int c0 = w * 128 + lane * 4;
    const ull ABSM = 0x7FFFFFFF7FFFFFFFull;
    const ull C06 = pk2(0.6f, 0.6f);
    const ull C04 = pk2(0.4f, 0.4f);
    float4 v;
    v = *(const float4*)(WeP + c0);        ull wp0A = pk2(v.x, v.y), wp0B = pk2(v.z, v.w);
    v = *(const float4*)(WeP + 256 + c0);  ull wp1A = pk2(v.x, v.y), wp1B = pk2(v.z, v.w);
    v = *(const float4*)(WeP + 512 + c0);  ull wp2A = pk2(v.x, v.y), wp2B = pk2(v.z, v.w);
    v = *(const float4*)(WeP + 768 + c0);  ull wp3A = pk2(v.x, v.y), wp3B = pk2(v.z, v.w);
    v = *(const float4*)(WeP + 1024 + c0); ull wp4A = pk2(v.x, v.y), wp4B = pk2(v.z, v.w);
    v = *(const float4*)(attF + c0);       ull attA = pk2(v.x, v.y), attB = pk2(v.z, v.w);
    v = *(const float4*)(g_xr + (long)n * 256 + c0);
    ull xrA = pk2(v.x, v.y), xrB = pk2(v.z, v.w);
    int d = g_deg[n];
    const int* lst = g_nodelist + n * MAXDEG;
    const int* sl  = g_srclist  + n * MAXDEG;
    float m = -1e30f, ssum = 0.f;
    ull accA = 0ull, accB = 0ull;
    __syncthreads();   // bsum/bsq init visible
    int i = 0;
    for (; i + 4 <= d; i += 4) {
        int4 ev = *(const int4*)(lst + i);
        int4 sv = *(const int4*)(sl + i);
        float4 xf0 = *(const float4*)(g_xl + (long)sv.x * 256 + c0);
        float4 xf1 = *(const float4*)(g_xl + (long)sv.y * 256 + c0);
        float4 xf2 = *(const float4*)(g_xl + (long)sv.z * 256 + c0);
        float4 xf3 = *(const float4*)(g_xl + (long)sv.w * 256 + c0);
        float4 a40 = g_ea4[ev.x]; float a10 = g_ea1[ev.x];
        float4 a41 = g_ea4[ev.y]; float a11 = g_ea1[ev.y];
        float4 a42 = g_ea4[ev.z]; float a12 = g_ea1[ev.z];
        float4 a43 = g_ea4[ev.w]; float a13 = g_ea1[ev.w];
        ull x0A = pk2(xf0.x, xf0.y), x0B = pk2(xf0.z, xf0.w);
        ull x1A = pk2(xf1.x, xf1.y), x1B = pk2(xf1.z, xf1.w);
        ull x2A = pk2(xf2.x, xf2.y), x2B = pk2(xf2.z, xf2.w);
        ull x3A = pk2(xf3.x, xf3.y), x3B = pk2(xf3.z, xf3.w);
        float p0, p1, p2, p3;
        {
            ull b0 = pk2(a40.x, a40.x), b1 = pk2(a40.y, a40.y), b2 = pk2(a40.z, a40.z),
                b3 = pk2(a40.w, a40.w), b4 = pk2(a10, a10);
            ull zA = add2_(x0A, xrA);
            zA = fma2_(b0, wp0A, zA); zA = fma2_(b1, wp1A, zA); zA = fma2_(b2, wp2A, zA);
            zA = fma2_(b3, wp3A, zA); zA = fma2_(b4, wp4A, zA);
            ull zB = add2_(x0B, xrB);
            zB = fma2_(b0, wp0B, zB); zB = fma2_(b1, wp1B, zB); zB = fma2_(b2, wp2B, zB);
            zB = fma2_(b3, wp3B, zB); zB = fma2_(b4, wp4B, zB);
            ull lA = fma2_(C06, zA, mul2_(C04, zA & ABSM));
            ull lB = fma2_(C06, zB, mul2_(C04, zB & ABSM));
            ull pp = fma2_(attA, lA, mul2_(attB, lB));
            float plo, phi; unpk2(plo, phi, pp);
            p0 = plo + phi;
        }
        {
            ull b0 = pk2(a41.x, a41.x), b1 = pk2(a41.y, a41.y), b2 = pk2(a41.z, a41.z),
                b3 = pk2(a41.w, a41.w), b4 = pk2(a11, a11);
            ull zA = add2_(x1A, xrA);
            zA = fma2_(b0, wp0A, zA); zA = fma2_(b1, wp1A, zA); zA = fma2_(b2, wp2A, zA);
            zA = fma2_(b3, wp3A, zA); zA = fma2_(b4, wp4A, zA);
            ull zB = add2_(x1B, xrB);
            zB = fma2_(b0, wp0B, zB); zB = fma2_(b1, wp1B, zB); zB = fma2_(b2, wp2B, zB);
            zB = fma2_(b3, wp3B, zB); zB = fma2_(b4, wp4B, zB);
            ull lA = fma2_(C06, zA, mul2_(C04, zA & ABSM));
            ull lB = fma2_(C06, zB, mul2_(C04, zB & ABSM));
            ull pp = fma2_(attA, lA, mul2_(attB, lB));
            float plo, phi; unpk2(plo, phi, pp);
            p1 = plo + phi;
        }
        {
            ull b0 = pk2(a42.x, a42.x), b1 = pk2(a42.y, a42.y), b2 = pk2(a42.z, a42.z),
                b3 = pk2(a42.w, a42.w), b4 = pk2(a12, a12);
            ull zA = add2_(x2A, xrA);
            zA = fma2_(b0, wp0A, zA); zA = fma2_(b1, wp1A, zA); zA = fma2_(b2, wp2A, zA);
            zA = fma2_(b3, wp3A, zA); zA = fma2_(b4, wp4A, zA);
            ull zB = add2_(x2B, xrB);
            zB = fma2_(b0, wp0B, zB); zB = fma2_(b1, wp1B, zB); zB = fma2_(b2, wp2B, zB);
            zB = fma2_(b3, wp3B, zB); zB = fma2_(b4, wp4B, zB);
            ull lA = fma2_(C06, zA, mul2_(C04, zA & ABSM));
            ull lB = fma2_(C06, zB, mul2_(C04, zB & ABSM));
            ull pp = fma2_(attA, lA, mul2_(attB, lB));
            float plo, phi; unpk2(plo, phi, pp);
            p2 = plo + phi;
        }
        {
            ull b0 = pk2(a43.x, a43.x), b1 = pk2(a43.y, a43.y), b2 = pk2(a43.z, a43.z),
                b3 = pk2(a43.w, a43.w), b4 = pk2(a13, a13);
            ull zA = add2_(x3A, xrA);
            zA = fma2_(b0, wp0A, zA); zA = fma2_(b1, wp1A, zA); zA = fma2_(b2, wp2A, zA);
            zA = fma2_(b3, wp3A, zA); zA = fma2_(b4, wp4A, zA);
            ull zB = add2_(x3B, xrB);
            zB = fma2_(b0, wp0B, zB); zB = fma2_(b1, wp1B, zB); zB = fma2_(b2, wp2B, zB);
            zB = fma2_(b3, wp3B, zB); zB = fma2_(b4, wp4B, zB);
            ull lA = fma2_(C06, zA, mul2_(C04, zA & ABSM));
            ull lB = fma2_(C06, zB, mul2_(C04, zB & ABSM));
            ull pp = fma2_(attA, lA, mul2_(attB, lB));
            float plo, phi; unpk2(plo, phi, pp);
            p3 = plo + phi;
        }
        #pragma unroll
        for (int o = 8; o; o >>= 1) {   // reduce within 16-lane half-warp (one head)
            p0 += __shfl_xor_sync(FULLMASK, p0, o);
            p1 += __shfl_xor_sync(FULLMASK, p1, o);
            p2 += __shfl_xor_sync(FULLMASK, p2, o);
            p3 += __shfl_xor_sync(FULLMASK, p3, o);
        }
        float mx = fmaxf(fmaxf(fmaxf(p0, p1), fmaxf(p2, p3)), m);
        float f  = __expf(m - mx);
        float w0 = __expf(p0 - mx), w1 = __expf(p1 - mx),
              w2 = __expf(p2 - mx), w3 = __expf(p3 - mx);
        ssum = ssum * f + ((w0 + w1) + (w2 + w3));
        ull fp = pk2(f, f);
        ull w0p = pk2(w0, w0), w1p = pk2(w1, w1), w2p = pk2(w2, w2), w3p = pk2(w3, w3);
        accA = fma2_(w0p, x0A, mul2_(accA, fp));
        accA = fma2_(w1p, x1A, accA);
        accA = fma2_(w2p, x2A, accA);
        accA = fma2_(w3p, x3A, accA);
        accB = fma2_(w0p, x0B, mul2_(accB, fp));
        accB = fma2_(w1p, x1B, accB);
        accB = fma2_(w2p, x2B, accB);
        accB = fma2_(w3p, x3B, accB);
        m = mx;
    }
    for (; i < d; i++) {
        int e = lst[i], s0 = sl[i];
        float4 xf0 = *(const float4*)(g_xl + (long)s0 * 256 + c0);
        float4 a4 = g_ea4[e]; float a1e = g_ea1[e];
        ull x0A = pk2(xf0.x, xf0.y), x0B = pk2(xf0.z, xf0.w);
        ull b0 = pk2(a4.x, a4.x), b1 = pk2(a4.y, a4.y), b2 = pk2(a4.z, a4.z),
            b3 = pk2(a4.w, a4.w), b4 = pk2(a1e, a1e);
        ull zA = add2_(x0A, xrA);
        zA = fma2_(b0, wp0A, zA); zA = fma2_(b1, wp1A, zA); zA = fma2_(b2, wp2A, zA);
        zA = fma2_(b3, wp3A, zA); zA = fma2_(b4, wp4A, zA);
        ull zB = add2_(x0B, xrB);
        zB = fma2_(b0, wp0B, zB); zB = fma2_(b1, wp1B, zB); zB = fma2_(b2, wp2B, zB);
        zB = fma2_(b3, wp3B, zB); zB = fma2_(b4, wp4B, zB);
        ull lA = fma2_(C06, zA, mul2_(C04, zA & ABSM));
        ull lB = fma2_(C06, zB, mul2_(C04, zB & ABSM));
        ull pp = fma2_(attA, lA, mul2_(attB, lB));
        float plo, phi; unpk2(plo, phi, pp);
        float p0 = plo + phi;
        #pragma unroll
        for (int o = 8; o; o >>= 1) p0 += __shfl_xor_sync(FULLMASK, p0, o);
        float mx = fmaxf(m, p0);
        float f = __expf(m - mx), w0 = __expf(p0 - mx);
        ssum = ssum * f + w0;
        ull fp = pk2(f, f);
        ull w0p = pk2(w0, w0);
        accA = fma2_(w0p, x0A, mul2_(accA, fp));
        accB = fma2_(w0p, x0B, mul2_(accB, fp));
        m = mx;
    }
    float inv = 1.f / (ssum + 1e-16f);
    float ax, ay, az, aw;
    unpk2(ax, ay, accA);
    unpk2(az, aw, accB);
    float4 o4 = make_float4(ax * inv, ay * inv, az * inv, aw * inv);
    *(float4*)(g_out + (long)n * 256 + c0) = o4;
    atomicAdd(&bsum[c0],     o4.x); atomicAdd(&bsq[c0],     o4.x * o4.x);
    atomicAdd(&bsum[c0 + 1], o4.y); atomicAdd(&bsq[c0 + 1], o4.y * o4.y);
    atomicAdd(&bsum[c0 + 2], o4.z); atomicAdd(&bsq[c0 + 2], o4.z * o4.z);
    atomicAdd(&bsum[c0 + 3], o4.w); atomicAdd(&bsq[c0 + 3], o4.w * o4.w);
    __syncthreads();
    if (t < HC) {
        atomicAdd(&csum[t], (double)bsum[t]);
        atomicAdd(&csq[t],  (double)bsq[t]);
    }
}

// ---------------- pool + classifier (BN+leaky of layer 1 fused in) -------------
__global__ void pool_k(const float* __restrict__ W, const float* __restrict__ bb,
                       const float* __restrict__ gam, const float* __restrict__ bet,
                       float* __restrict__ outp) {
    int g = blockIdx.x;
    int t = threadIdx.x;  // 256 = channel
    double mu_d  = g_csum1[t] * (1.0 / NN);
    double var_d = g_csq1[t] * (1.0 / NN) - mu_d * mu_d;
    float mu = (float)mu_d;
    float rs = rsqrtf((float)var_d + 1e-5f) * gam[t];
    float bt = bet[t];
    float s = 0.f;
    int base = g * N_ROI;
    for (int r = 0; r < N_ROI; r++) {
        float v = g_out[(base + r) * 256 + t];
        v = (v - mu) * rs + bt;
        v = v >= 0.f ? v : 0.01f * v;
        s += v;
    }
    s *= (1.f / (float)N_ROI);
    float c0 = s * W[t * 2], c1 = s * W[t * 2 + 1];
    __shared__ float r0s[8], r1s[8];
    for (int o = 16; o; o >>= 1) {
        c0 += __shfl_down_sync(FULLMASK, c0, o);
        c1 += __shfl_down_sync(FULLMASK, c1, o);
    }
    if ((t & 31) == 0) { r0s[t >> 5] = c0; r1s[t >> 5] = c1; }
    __syncthreads();
    if (t == 0) {
        float a = 0.f, b2 = 0.f;
        for (int i = 0; i < 8; i++) { a += r0s[i]; b2 += r1s[i]; }
        outp[g * 2]     = a  + bb[0];
        outp[g * 2 + 1] = b2 + bb[1];
    }
}

// ---------------- launch --------------------------------------------------------
extern "C" void kernel_launch(void* const* d_in, const int* in_sizes, int n_in,
                              void* d_out, int out_size) {
    const float* x          = (const float*)d_in[0];
    const int*   edge_index = (const int*)  d_in[1];
    const float* edge_attr  = (const float*)d_in[2];
    const int*   node_group = (const int*)  d_in[4];
    const float* group_emb  = (const float*)d_in[5];
    const float* W_embed    = (const float*)d_in[6];
    const float* b_embed    = (const float*)d_in[7];
    const float* We_enc     = (const float*)d_in[8];
    const float* be_enc     = (const float*)d_in[9];
    const float* W1         = (const float*)d_in[10];
    const float* b1         = (const float*)d_in[11];
    const float* W2         = (const float*)d_in[12];
    const float* b2         = (const float*)d_in[13];
    const float* ln_g       = (const float*)d_in[14];
    const float* ln_b       = (const float*)d_in[15];
    const float* l0_Wl      = (const float*)d_in[16];
    const float* l0_Wr      = (const float*)d_in[17];
    const float* l0_We      = (const float*)d_in[18];
    const float* l0_att     = (const float*)d_in[19];
    const float* l0_bn_g    = (const float*)d_in[21];
    const float* l0_bn_b    = (const float*)d_in[22];
    const float* l1_Wl      = (const float*)d_in[23];
    const float* l1_Wr      = (const float*)d_in[24];
    const float* l1_We      = (const float*)d_in[25];
    const float* l1_att     = (const float*)d_in[26];
    const float* l1_bn_g    = (const float*)d_in[28];
    const float* l1_bn_b    = (const float*)d_in[29];
    const float* fc2_W      = (const float*)d_in[30];
    const float* fc2_b      = (const float*)d_in[31];

    const int* srcp = edge_index;
    const int* dstp = edge_index + EE;

    double* csum0; double* csq0; double* csum1; double* csq1;
    cudaGetSymbolAddress((void**)&csum0, g_csum0);
    cudaGetSymbolAddress((void**)&csq0,  g_csq0);
    cudaGetSymbolAddress((void**)&csum1, g_csum1);
    cudaGetSymbolAddress((void**)&csq1,  g_csq1);

    prologue_k<<<PB_TOTAL, 256>>>(x, node_group, group_emb, W_embed, b_embed,
                                  srcp, dstp, edge_attr);
    gine_k<<<NN, 64>>>(We_enc, be_enc, W1, b1, W2, b2, ln_g, ln_b);
    xlxr0_k<<<NN / 16, 256>>>(l0_Wl, l0_Wr);
    // 4 (profiled): GAT layer 0
    gat_warp_k<<<NN / 4, 256>>>(l0_We, l0_att, csum0, csq0);
    xlxr1_k<<<NN / 16, 256>>>(l1_Wl, l1_Wr, l0_bn_g, l0_bn_b);
    gat_warp_k<<<NN / 4, 256>>>(l1_We, l1_att, csum1, csq1);
    pool_k<<<G, 256>>>(fc2_W, fc2_b, l1_bn_g, l1_bn_b, (float*)d_out);
}